// round 1
// baseline (speedup 1.0000x reference)
#include <cuda_runtime.h>
#include <math.h>

#define N_TOK 8192
#define HDIM  1024
#define NEXP  16
#define TOPK  4
#define NPAIR (N_TOK * TOPK)          // 32768
#define NBLK_TOPK (N_TOK / 256)       // 32

// ---------------- device scratch (no cudaMalloc allowed) ----------------
__device__ int   g_counts[NEXP];
__device__ int   g_pairs[NEXP * NPAIR];          // pair id = token*4 + slot
__device__ float g_partial[NBLK_TOPK * NEXP];    // per-block score sums
__device__ float g_t[(size_t)NPAIR * HDIM];      // silu(gate)*up intermediate (128 MB)

// ---------------- kernel 0: reset counters ----------------
__global__ void k_init() {
    if (threadIdx.x < NEXP) g_counts[threadIdx.x] = 0;
}

// ---------------- kernel 1: top-4 routing + score partial sums ----------------
__global__ void k_topk(const float* __restrict__ scores) {
    __shared__ float ssum[256][NEXP];
    const int tid = threadIdx.x;
    const int n = blockIdx.x * 256 + tid;

    float v[NEXP];
#pragma unroll
    for (int e = 0; e < NEXP; e++) v[e] = scores[(size_t)n * NEXP + e];
#pragma unroll
    for (int e = 0; e < NEXP; e++) ssum[tid][e] = v[e];

    // top-4, ties -> lowest index (matches jax.lax.top_k)
    bool used[NEXP];
#pragma unroll
    for (int e = 0; e < NEXP; e++) used[e] = false;
#pragma unroll
    for (int slot = 0; slot < TOPK; slot++) {
        float best = -1e30f; int bi = 0;
#pragma unroll
        for (int e = 0; e < NEXP; e++) {
            if (!used[e] && v[e] > best) { best = v[e]; bi = e; }
        }
        used[bi] = true;
        int pos = atomicAdd(&g_counts[bi], 1);
        g_pairs[bi * NPAIR + pos] = n * TOPK + slot;
    }

    // deterministic in-block reduction of score sums
    __syncthreads();
    for (int s = 128; s > 0; s >>= 1) {
        if (tid < s) {
#pragma unroll
            for (int e = 0; e < NEXP; e++) ssum[tid][e] += ssum[tid + s][e];
        }
        __syncthreads();
    }
    if (tid < NEXP) g_partial[blockIdx.x * NEXP + tid] = ssum[0][tid];
}

// ---------------- kernel 2: aux loss scalar ----------------
__global__ void k_aux(float* __restrict__ dst) {
    __shared__ float se[NEXP];
    const int e = threadIdx.x;
    if (e < NEXP) {
        float s = 0.0f;
        for (int b = 0; b < NBLK_TOPK; b++) s += g_partial[b * NEXP + e];
        se[e] = s * (float)g_counts[e];
    }
    __syncthreads();
    if (e == 0) {
        float t = 0.0f;
#pragma unroll
        for (int i = 0; i < NEXP; i++) t += se[i];
        // aux = ALPHA * E * sum_e (Se/N) * (cnt_e/(N*K))
        dst[0] = t * (0.001f * (float)NEXP / ((float)N_TOK * (float)NPAIR));
    }
}

// ---------------- kernel 3: fused gate/up GEMM + silu*up epilogue ----------------
// out rows: gathered tokens of expert e. t[p, i] = silu(x.Wg[e,i,:]) * (x.Wu[e,i,:])
// BM=128, BN=64 (per matrix), BK=32, 256 threads, 8x4 microtile per matrix.
__global__ __launch_bounds__(256) void k_gemm1(const float* __restrict__ X,
                                               const float* __restrict__ Wg,
                                               const float* __restrict__ Wu) {
    __shared__ float As[32][132];
    __shared__ float Bg[32][68];
    __shared__ float Bu[32][68];
    __shared__ int   spid[128];

    const int e = blockIdx.z;
    const int cnt = g_counts[e];
    const int mbase = blockIdx.y * 128;
    if (mbase >= cnt) return;

    const int tid = threadIdx.x;
    if (tid < 128) {
        int r = mbase + tid;
        spid[tid] = (r < cnt) ? g_pairs[e * NPAIR + r] : -1;
    }
    __syncthreads();

    const int n0 = blockIdx.x * 64;
    const float* wg = Wg + (size_t)e * HDIM * HDIM;
    const float* wu = Wu + (size_t)e * HDIM * HDIM;

    const int lr = tid >> 3;        // 0..31
    const int lc = (tid & 7) * 4;   // 0,4,...,28
    const int m0 = (tid >> 4) * 8;  // 0..120
    const int nn = (tid & 15) * 4;  // 0..60

    float ag[8][4], au[8][4];
#pragma unroll
    for (int i = 0; i < 8; i++)
#pragma unroll
        for (int j = 0; j < 4; j++) { ag[i][j] = 0.0f; au[i][j] = 0.0f; }

    for (int k0 = 0; k0 < HDIM; k0 += 32) {
#pragma unroll
        for (int it = 0; it < 4; it++) {
            int r = lr + it * 32;
            int p = spid[r];
            float4 v = make_float4(0.f, 0.f, 0.f, 0.f);
            if (p >= 0) v = *(const float4*)(X + (size_t)(p >> 2) * HDIM + k0 + lc);
            As[lc + 0][r] = v.x; As[lc + 1][r] = v.y;
            As[lc + 2][r] = v.z; As[lc + 3][r] = v.w;
        }
#pragma unroll
        for (int it = 0; it < 2; it++) {
            int r = lr + it * 32;  // 0..63
            const size_t off = (size_t)(n0 + r) * HDIM + k0 + lc;
            float4 vg = *(const float4*)(wg + off);
            float4 vu = *(const float4*)(wu + off);
            Bg[lc + 0][r] = vg.x; Bg[lc + 1][r] = vg.y;
            Bg[lc + 2][r] = vg.z; Bg[lc + 3][r] = vg.w;
            Bu[lc + 0][r] = vu.x; Bu[lc + 1][r] = vu.y;
            Bu[lc + 2][r] = vu.z; Bu[lc + 3][r] = vu.w;
        }
        __syncthreads();

#pragma unroll
        for (int kk = 0; kk < 32; kk++) {
            float4 a0 = *(const float4*)&As[kk][m0];
            float4 a1 = *(const float4*)&As[kk][m0 + 4];
            float4 bgv = *(const float4*)&Bg[kk][nn];
            float4 buv = *(const float4*)&Bu[kk][nn];
            float a[8]  = {a0.x, a0.y, a0.z, a0.w, a1.x, a1.y, a1.z, a1.w};
            float bg4[4] = {bgv.x, bgv.y, bgv.z, bgv.w};
            float bu4[4] = {buv.x, buv.y, buv.z, buv.w};
#pragma unroll
            for (int i = 0; i < 8; i++) {
#pragma unroll
                for (int j = 0; j < 4; j++) {
                    ag[i][j] += a[i] * bg4[j];
                    au[i][j] += a[i] * bu4[j];
                }
            }
        }
        __syncthreads();
    }

    // epilogue: t = silu(g) * u
#pragma unroll
    for (int i = 0; i < 8; i++) {
        int p = spid[m0 + i];
        if (p < 0) continue;
        float4 o;
        float* op = (float*)&o;
#pragma unroll
        for (int j = 0; j < 4; j++) {
            float g = ag[i][j];
            float s = g / (1.0f + __expf(-g));
            op[j] = s * au[i][j];
        }
        *(float4*)(g_t + (size_t)p * HDIM + n0 + nn) = o;
    }
}

// ---------------- kernel 4: down GEMM + relu, scatter to output ----------------
// out[p, h] = relu( sum_i t[p,i] * Wd[e,h,i] )
// BM=128, BN=128, BK=32, 256 threads, 8x8 microtile.
__global__ __launch_bounds__(256) void k_gemm2(const float* __restrict__ Wd,
                                               float* __restrict__ out) {
    __shared__ float As[32][132];
    __shared__ float Bs[32][132];
    __shared__ int   spid[128];

    const int e = blockIdx.z;
    const int cnt = g_counts[e];
    const int mbase = blockIdx.y * 128;
    if (mbase >= cnt) return;

    const int tid = threadIdx.x;
    if (tid < 128) {
        int r = mbase + tid;
        spid[tid] = (r < cnt) ? g_pairs[e * NPAIR + r] : -1;
    }
    __syncthreads();

    const int n0 = blockIdx.x * 128;
    const float* wd = Wd + (size_t)e * HDIM * HDIM;

    const int lr = tid >> 3;
    const int lc = (tid & 7) * 4;
    const int m0 = (tid >> 4) * 8;
    const int nn = (tid & 15) * 8;

    float acc[8][8];
#pragma unroll
    for (int i = 0; i < 8; i++)
#pragma unroll
        for (int j = 0; j < 8; j++) acc[i][j] = 0.0f;

    for (int k0 = 0; k0 < HDIM; k0 += 32) {
#pragma unroll
        for (int it = 0; it < 4; it++) {
            int r = lr + it * 32;
            int p = spid[r];
            float4 v = make_float4(0.f, 0.f, 0.f, 0.f);
            if (p >= 0) v = *(const float4*)(g_t + (size_t)p * HDIM + k0 + lc);
            As[lc + 0][r] = v.x; As[lc + 1][r] = v.y;
            As[lc + 2][r] = v.z; As[lc + 3][r] = v.w;
        }
#pragma unroll
        for (int it = 0; it < 4; it++) {
            int r = lr + it * 32;  // 0..127
            float4 v = *(const float4*)(wd + (size_t)(n0 + r) * HDIM + k0 + lc);
            Bs[lc + 0][r] = v.x; Bs[lc + 1][r] = v.y;
            Bs[lc + 2][r] = v.z; Bs[lc + 3][r] = v.w;
        }
        __syncthreads();

#pragma unroll
        for (int kk = 0; kk < 32; kk++) {
            float4 a0 = *(const float4*)&As[kk][m0];
            float4 a1 = *(const float4*)&As[kk][m0 + 4];
            float4 b0 = *(const float4*)&Bs[kk][nn];
            float4 b1 = *(const float4*)&Bs[kk][nn + 4];
            float a[8] = {a0.x, a0.y, a0.z, a0.w, a1.x, a1.y, a1.z, a1.w};
            float b[8] = {b0.x, b0.y, b0.z, b0.w, b1.x, b1.y, b1.z, b1.w};
#pragma unroll
            for (int i = 0; i < 8; i++)
#pragma unroll
                for (int j = 0; j < 8; j++) acc[i][j] += a[i] * b[j];
        }
        __syncthreads();
    }

#pragma unroll
    for (int i = 0; i < 8; i++) {
        int p = spid[m0 + i];
        if (p < 0) continue;
        float4 o0, o1;
        o0.x = fmaxf(acc[i][0], 0.f); o0.y = fmaxf(acc[i][1], 0.f);
        o0.z = fmaxf(acc[i][2], 0.f); o0.w = fmaxf(acc[i][3], 0.f);
        o1.x = fmaxf(acc[i][4], 0.f); o1.y = fmaxf(acc[i][5], 0.f);
        o1.z = fmaxf(acc[i][6], 0.f); o1.w = fmaxf(acc[i][7], 0.f);
        float* dst = out + (size_t)p * HDIM + n0 + nn;
        *(float4*)(dst + 0) = o0;
        *(float4*)(dst + 4) = o1;
    }
}

// ---------------- launch ----------------
extern "C" void kernel_launch(void* const* d_in, const int* in_sizes, int n_in,
                              void* d_out, int out_size) {
    const float* X      = (const float*)d_in[0];
    const float* scores = (const float*)d_in[1];
    const float* Wg     = (const float*)d_in[2];
    const float* Wu     = (const float*)d_in[3];
    const float* Wd     = (const float*)d_in[4];
    float* out = (float*)d_out;

    k_init<<<1, 32>>>();
    k_topk<<<NBLK_TOPK, 256>>>(scores);
    k_aux<<<1, 32>>>(out + (out_size - 1));

    dim3 g1(HDIM / 64, NPAIR / 128, NEXP);   // (16, 256, 16); dead m-tiles exit fast
    k_gemm1<<<g1, 256>>>(X, Wg, Wu);

    dim3 g2(HDIM / 128, NPAIR / 128, NEXP);  // (8, 256, 16)
    k_gemm2<<<g2, 256>>>(Wd, out);
}

// round 3
// speedup vs baseline: 2.3461x; 2.3461x over previous
#include <cuda_runtime.h>
#include <cuda_bf16.h>
#include <stdint.h>
#include <math.h>

#define N_TOK 8192
#define HDIM  1024
#define NEXP  16
#define TOPK  4
#define NPAIR (N_TOK * TOPK)          // 32768
#define NBLK_TOPK (N_TOK / 256)       // 32
#define CHUNK 64                      // K per pipeline stage
#define NCHUNK (HDIM / CHUNK)         // 16
#define LDS 144                       // smem row stride (bytes): 128B data + 16B pad
#define STAGE 73728                   // bytes per stage (A hi/lo + B hi/lo)
#define SMEM_DYN (2 * STAGE)

// ---------------- device scratch ----------------
__device__ int   g_counts[NEXP];
__device__ int   g_pairs[NEXP * NPAIR];
__device__ float g_partial[NBLK_TOPK * NEXP];
__device__ __nv_bfloat16 g_Xhi[(size_t)N_TOK * HDIM];
__device__ __nv_bfloat16 g_Xlo[(size_t)N_TOK * HDIM];
__device__ __nv_bfloat16 g_Wghi[(size_t)NEXP * HDIM * HDIM];
__device__ __nv_bfloat16 g_Wglo[(size_t)NEXP * HDIM * HDIM];
__device__ __nv_bfloat16 g_Wuhi[(size_t)NEXP * HDIM * HDIM];
__device__ __nv_bfloat16 g_Wulo[(size_t)NEXP * HDIM * HDIM];
__device__ __nv_bfloat16 g_Wdhi[(size_t)NEXP * HDIM * HDIM];
__device__ __nv_bfloat16 g_Wdlo[(size_t)NEXP * HDIM * HDIM];
__device__ __nv_bfloat16 g_thi[(size_t)NPAIR * HDIM];
__device__ __nv_bfloat16 g_tlo[(size_t)NPAIR * HDIM];

// ---------------- helpers ----------------
__device__ __forceinline__ uint32_t smem_u32(const void* p) {
    uint32_t a;
    asm("{ .reg .u64 t; cvta.to.shared.u64 t, %1; cvt.u32.u64 %0, t; }" : "=r"(a) : "l"(p));
    return a;
}
__device__ __forceinline__ void ldm4(uint32_t* r, uint32_t a) {
    asm volatile("ldmatrix.sync.aligned.m8n8.x4.shared.b16 {%0,%1,%2,%3}, [%4];"
                 : "=r"(r[0]), "=r"(r[1]), "=r"(r[2]), "=r"(r[3]) : "r"(a));
}
__device__ __forceinline__ void mma16816(float* d, const uint32_t* a, const uint32_t* b) {
    asm volatile("mma.sync.aligned.m16n8k16.row.col.f32.bf16.bf16.f32 "
                 "{%0,%1,%2,%3},{%4,%5,%6,%7},{%8,%9},{%0,%1,%2,%3};"
                 : "+f"(d[0]), "+f"(d[1]), "+f"(d[2]), "+f"(d[3])
                 : "r"(a[0]), "r"(a[1]), "r"(a[2]), "r"(a[3]), "r"(b[0]), "r"(b[1]));
}
#define CPA(dst, src, sz) asm volatile("cp.async.cg.shared.global [%0],[%1],16,%2;" :: "r"(dst), "l"(src), "r"(sz))
#define CPC()   asm volatile("cp.async.commit_group;")
#define CPW(n)  asm volatile("cp.async.wait_group %0;" :: "n"(n))

__device__ __forceinline__ void split4(float4 v, uint2& h, uint2& l) {
    __nv_bfloat16 hx = __float2bfloat16(v.x), hy = __float2bfloat16(v.y);
    __nv_bfloat16 hz = __float2bfloat16(v.z), hw = __float2bfloat16(v.w);
    __nv_bfloat16 lx = __float2bfloat16(v.x - __bfloat162float(hx));
    __nv_bfloat16 ly = __float2bfloat16(v.y - __bfloat162float(hy));
    __nv_bfloat16 lz = __float2bfloat16(v.z - __bfloat162float(hz));
    __nv_bfloat16 lw = __float2bfloat16(v.w - __bfloat162float(hw));
    h.x = (uint32_t)__bfloat16_as_ushort(hx) | ((uint32_t)__bfloat16_as_ushort(hy) << 16);
    h.y = (uint32_t)__bfloat16_as_ushort(hz) | ((uint32_t)__bfloat16_as_ushort(hw) << 16);
    l.x = (uint32_t)__bfloat16_as_ushort(lx) | ((uint32_t)__bfloat16_as_ushort(ly) << 16);
    l.y = (uint32_t)__bfloat16_as_ushort(lz) | ((uint32_t)__bfloat16_as_ushort(lw) << 16);
}

// ---------------- routing + aux (proven) ----------------
__global__ void k_init() { if (threadIdx.x < NEXP) g_counts[threadIdx.x] = 0; }

__global__ void k_topk(const float* __restrict__ scores) {
    __shared__ float ssum[256][NEXP];
    const int tid = threadIdx.x;
    const int n = blockIdx.x * 256 + tid;
    float v[NEXP];
#pragma unroll
    for (int e = 0; e < NEXP; e++) v[e] = scores[(size_t)n * NEXP + e];
#pragma unroll
    for (int e = 0; e < NEXP; e++) ssum[tid][e] = v[e];
    bool used[NEXP];
#pragma unroll
    for (int e = 0; e < NEXP; e++) used[e] = false;
#pragma unroll
    for (int slot = 0; slot < TOPK; slot++) {
        float best = -1e30f; int bi = 0;
#pragma unroll
        for (int e = 0; e < NEXP; e++)
            if (!used[e] && v[e] > best) { best = v[e]; bi = e; }
        used[bi] = true;
        int pos = atomicAdd(&g_counts[bi], 1);
        g_pairs[bi * NPAIR + pos] = n * TOPK + slot;
    }
    __syncthreads();
    for (int s = 128; s > 0; s >>= 1) {
        if (tid < s)
#pragma unroll
            for (int e = 0; e < NEXP; e++) ssum[tid][e] += ssum[tid + s][e];
        __syncthreads();
    }
    if (tid < NEXP) g_partial[blockIdx.x * NEXP + tid] = ssum[0][tid];
}

__global__ void k_aux(float* __restrict__ dst) {
    __shared__ float se[NEXP];
    const int e = threadIdx.x;
    if (e < NEXP) {
        float s = 0.0f;
        for (int b = 0; b < NBLK_TOPK; b++) s += g_partial[b * NEXP + e];
        se[e] = s * (float)g_counts[e];
    }
    __syncthreads();
    if (e == 0) {
        float t = 0.0f;
#pragma unroll
        for (int i = 0; i < NEXP; i++) t += se[i];
        dst[0] = t * (0.001f * (float)NEXP / ((float)N_TOK * (float)NPAIR));
    }
}

// ---------------- precompute bf16 hi/lo splits ----------------
__global__ void k_split_x(const float4* __restrict__ src) {
    int i = blockIdx.x * 256 + threadIdx.x;      // n4 = 2097152
    float4 v = src[i];
    uint2 h, l; split4(v, h, l);
    ((uint2*)g_Xhi)[i] = h;
    ((uint2*)g_Xlo)[i] = l;
}
__global__ void k_split_w(const float4* __restrict__ src, int which) {
    int i = blockIdx.x * 256 + threadIdx.x;      // n4 = 4194304
    float4 v = src[i];
    uint2 h, l; split4(v, h, l);
    __nv_bfloat16* hi = (which == 0) ? g_Wghi : (which == 1) ? g_Wuhi : g_Wdhi;
    __nv_bfloat16* lo = (which == 0) ? g_Wglo : (which == 1) ? g_Wulo : g_Wdlo;
    ((uint2*)hi)[i] = h;
    ((uint2*)lo)[i] = l;
}

// ---------------- GEMM1: gate+up (bf16x3 HMMA) + silu*mul, writes t hi/lo ----------
// BM=128 pairs, per-CTA 64 cols of BOTH Wg and Wu, BK=64.
// smem stage: AH 0, AL 18432, BGH 36864, BGL 46080, BUH 55296, BUL 64512.
__global__ __launch_bounds__(256, 1) void k_gemm1() {
    const int e = blockIdx.z;
    const int cnt = g_counts[e];
    const int mbase = blockIdx.y * 128;
    if (mbase >= cnt) return;

    extern __shared__ char dyn[];
    __shared__ int spid[128];
    const int tid = threadIdx.x;
    if (tid < 128) {
        int r = mbase + tid;
        spid[tid] = (r < cnt) ? g_pairs[e * NPAIR + r] : -1;
    }
    __syncthreads();

    const uint32_t sbase = smem_u32(dyn);
    const int n0 = blockIdx.x * 64;
    const __nv_bfloat16* GH = g_Wghi + (size_t)e * HDIM * HDIM;
    const __nv_bfloat16* GL = g_Wglo + (size_t)e * HDIM * HDIM;
    const __nv_bfloat16* UH = g_Wuhi + (size_t)e * HDIM * HDIM;
    const __nv_bfloat16* UL = g_Wulo + (size_t)e * HDIM * HDIM;

    const int lr = tid >> 3;   // 0..31
    const int lc = tid & 7;    // 16B chunk within 64-k row

    auto load_stage = [&](int s, int k0) {
        uint32_t st = sbase + s * STAGE;
#pragma unroll
        for (int i = 0; i < 4; i++) {          // A: 128 rows, gathered tokens
            int r = lr + i * 32;
            int p = spid[r];
            int tok = (p >= 0) ? (p >> 2) : 0;
            size_t so = (size_t)tok * HDIM + k0 + lc * 8;
            uint32_t d = st + r * LDS + lc * 16;
            int sz = (p >= 0) ? 16 : 0;
            CPA(d,         g_Xhi + so, sz);
            CPA(d + 18432, g_Xlo + so, sz);
        }
#pragma unroll
        for (int i = 0; i < 2; i++) {          // B: 64 rows each of Wg, Wu
            int r = lr + i * 32;
            size_t so = (size_t)(n0 + r) * HDIM + k0 + lc * 8;
            uint32_t d = st + 36864 + r * LDS + lc * 16;
            CPA(d,         GH + so, 16);
            CPA(d + 9216,  GL + so, 16);
            CPA(d + 18432, UH + so, 16);
            CPA(d + 27648, UL + so, 16);
        }
        CPC();
    };

    const int wid = tid >> 5, lane = tid & 31;
    const int wm = (wid & 3) * 32;             // 4 warps over M
    const int wn = (wid >> 2) * 32;            // 2 warps over N(64)
    const uint32_t rowA = (uint32_t)(wm + (lane & 15)) * LDS + ((lane >> 4) & 1) * 16;
    const uint32_t rowB = (uint32_t)(wn + ((lane >> 4) & 1) * 8 + (lane & 7)) * LDS + ((lane >> 3) & 1) * 16;

    float accg[32], accu[32];
#pragma unroll
    for (int i = 0; i < 32; i++) { accg[i] = 0.f; accu[i] = 0.f; }

    load_stage(0, 0);
    for (int c = 0; c < NCHUNK; c++) {
        if (c + 1 < NCHUNK) { load_stage((c + 1) & 1, (c + 1) * CHUNK); CPW(1); }
        else CPW(0);
        __syncthreads();
        uint32_t st = sbase + (c & 1) * STAGE;
#pragma unroll
        for (int kk = 0; kk < 4; kk++) {
            uint32_t Ah[8], Al[8], BGh[8], BGl[8], BUh[8], BUl[8];
#pragma unroll
            for (int mi = 0; mi < 2; mi++) {
                ldm4(&Ah[mi * 4], st + rowA + mi * 16 * LDS + kk * 32);
                ldm4(&Al[mi * 4], st + 18432 + rowA + mi * 16 * LDS + kk * 32);
            }
#pragma unroll
            for (int nj = 0; nj < 2; nj++) {
                ldm4(&BGh[nj * 4], st + 36864 + rowB + nj * 16 * LDS + kk * 32);
                ldm4(&BGl[nj * 4], st + 46080 + rowB + nj * 16 * LDS + kk * 32);
                ldm4(&BUh[nj * 4], st + 55296 + rowB + nj * 16 * LDS + kk * 32);
                ldm4(&BUl[nj * 4], st + 64512 + rowB + nj * 16 * LDS + kk * 32);
            }
#pragma unroll
            for (int mi = 0; mi < 2; mi++)
#pragma unroll
                for (int ni = 0; ni < 4; ni++) {
                    float* dg = &accg[(mi * 4 + ni) * 4];
                    float* du = &accu[(mi * 4 + ni) * 4];
                    mma16816(dg, &Ah[mi * 4], &BGh[ni * 2]);
                    mma16816(dg, &Al[mi * 4], &BGh[ni * 2]);
                    mma16816(dg, &Ah[mi * 4], &BGl[ni * 2]);
                    mma16816(du, &Ah[mi * 4], &BUh[ni * 2]);
                    mma16816(du, &Al[mi * 4], &BUh[ni * 2]);
                    mma16816(du, &Ah[mi * 4], &BUl[ni * 2]);
                }
        }
        __syncthreads();
    }

    // epilogue: t = silu(g) * u, pre-split to bf16 hi/lo
    const int r0 = wm + (lane >> 2);
    const int coff = (lane & 3) * 2;
#pragma unroll
    for (int mi = 0; mi < 2; mi++) {
#pragma unroll
        for (int half = 0; half < 2; half++) {
            int row = r0 + mi * 16 + half * 8;
            int p = spid[row];
            if (p < 0) continue;
#pragma unroll
            for (int ni = 0; ni < 4; ni++) {
                const float* dg = &accg[(mi * 4 + ni) * 4 + half * 2];
                const float* du = &accu[(mi * 4 + ni) * 4 + half * 2];
                float v0 = du[0] * dg[0] / (1.0f + __expf(-dg[0]));
                float v1 = du[1] * dg[1] / (1.0f + __expf(-dg[1]));
                __nv_bfloat16 h0 = __float2bfloat16(v0), h1 = __float2bfloat16(v1);
                __nv_bfloat16 l0 = __float2bfloat16(v0 - __bfloat162float(h0));
                __nv_bfloat16 l1 = __float2bfloat16(v1 - __bfloat162float(h1));
                uint32_t hp = (uint32_t)__bfloat16_as_ushort(h0) | ((uint32_t)__bfloat16_as_ushort(h1) << 16);
                uint32_t lp = (uint32_t)__bfloat16_as_ushort(l0) | ((uint32_t)__bfloat16_as_ushort(l1) << 16);
                size_t off = (size_t)p * HDIM + n0 + wn + ni * 8 + coff;
                *(uint32_t*)(g_thi + off) = hp;
                *(uint32_t*)(g_tlo + off) = lp;
            }
        }
    }
}

// ---------------- GEMM2: down proj (bf16x3 HMMA) + relu -> out ----------------
// BM=128 pairs, BN=128 cols, BK=64. smem stage: AH 0, AL 18432, BH 36864, BL 55296.
__global__ __launch_bounds__(256, 1) void k_gemm2(float* __restrict__ out) {
    const int e = blockIdx.z;
    const int cnt = g_counts[e];
    const int mbase = blockIdx.y * 128;
    if (mbase >= cnt) return;

    extern __shared__ char dyn[];
    __shared__ int spid[128];
    const int tid = threadIdx.x;
    if (tid < 128) {
        int r = mbase + tid;
        spid[tid] = (r < cnt) ? g_pairs[e * NPAIR + r] : -1;
    }
    __syncthreads();

    const uint32_t sbase = smem_u32(dyn);
    const int n0 = blockIdx.x * 128;
    const __nv_bfloat16* WH = g_Wdhi + (size_t)e * HDIM * HDIM;
    const __nv_bfloat16* WL = g_Wdlo + (size_t)e * HDIM * HDIM;

    const int lr = tid >> 3;
    const int lc = tid & 7;

    auto load_stage = [&](int s, int k0) {
        uint32_t st = sbase + s * STAGE;
#pragma unroll
        for (int i = 0; i < 4; i++) {          // A: gathered t rows
            int r = lr + i * 32;
            int p = spid[r];
            int pp = (p >= 0) ? p : 0;
            size_t so = (size_t)pp * HDIM + k0 + lc * 8;
            uint32_t d = st + r * LDS + lc * 16;
            int sz = (p >= 0) ? 16 : 0;
            CPA(d,         g_thi + so, sz);
            CPA(d + 18432, g_tlo + so, sz);
        }
#pragma unroll
        for (int i = 0; i < 4; i++) {          // B: 128 rows of Wd
            int r = lr + i * 32;
            size_t so = (size_t)(n0 + r) * HDIM + k0 + lc * 8;
            uint32_t d = st + 36864 + r * LDS + lc * 16;
            CPA(d,         WH + so, 16);
            CPA(d + 18432, WL + so, 16);
        }
        CPC();
    };

    const int wid = tid >> 5, lane = tid & 31;
    const int wm = (wid & 3) * 32;
    const int wn = (wid >> 2) * 64;
    const uint32_t rowA = (uint32_t)(wm + (lane & 15)) * LDS + ((lane >> 4) & 1) * 16;
    const uint32_t rowB = (uint32_t)(wn + ((lane >> 4) & 1) * 8 + (lane & 7)) * LDS + ((lane >> 3) & 1) * 16;

    float acc[64];
#pragma unroll
    for (int i = 0; i < 64; i++) acc[i] = 0.f;

    load_stage(0, 0);
    for (int c = 0; c < NCHUNK; c++) {
        if (c + 1 < NCHUNK) { load_stage((c + 1) & 1, (c + 1) * CHUNK); CPW(1); }
        else CPW(0);
        __syncthreads();
        uint32_t st = sbase + (c & 1) * STAGE;
#pragma unroll
        for (int kk = 0; kk < 4; kk++) {
            uint32_t Ah[8], Al[8], Bh[16], Bl[16];
#pragma unroll
            for (int mi = 0; mi < 2; mi++) {
                ldm4(&Ah[mi * 4], st + rowA + mi * 16 * LDS + kk * 32);
                ldm4(&Al[mi * 4], st + 18432 + rowA + mi * 16 * LDS + kk * 32);
            }
#pragma unroll
            for (int nj = 0; nj < 4; nj++) {
                ldm4(&Bh[nj * 4], st + 36864 + rowB + nj * 16 * LDS + kk * 32);
                ldm4(&Bl[nj * 4], st + 55296 + rowB + nj * 16 * LDS + kk * 32);
            }
#pragma unroll
            for (int mi = 0; mi < 2; mi++)
#pragma unroll
                for (int ni = 0; ni < 8; ni++) {
                    float* d = &acc[(mi * 8 + ni) * 4];
                    mma16816(d, &Ah[mi * 4], &Bh[ni * 2]);
                    mma16816(d, &Al[mi * 4], &Bh[ni * 2]);
                    mma16816(d, &Ah[mi * 4], &Bl[ni * 2]);
                }
        }
        __syncthreads();
    }

    const int r0 = wm + (lane >> 2);
    const int coff = (lane & 3) * 2;
#pragma unroll
    for (int mi = 0; mi < 2; mi++) {
#pragma unroll
        for (int half = 0; half < 2; half++) {
            int row = r0 + mi * 16 + half * 8;
            int p = spid[row];
            if (p < 0) continue;
#pragma unroll
            for (int ni = 0; ni < 8; ni++) {
                const float* d = &acc[(mi * 8 + ni) * 4 + half * 2];
                float2 v;
                v.x = fmaxf(d[0], 0.f);
                v.y = fmaxf(d[1], 0.f);
                *(float2*)(out + (size_t)p * HDIM + n0 + wn + ni * 8 + coff) = v;
            }
        }
    }
}

// ---------------- launch ----------------
extern "C" void kernel_launch(void* const* d_in, const int* in_sizes, int n_in,
                              void* d_out, int out_size) {
    const float* X      = (const float*)d_in[0];
    const float* scores = (const float*)d_in[1];
    const float* Wg     = (const float*)d_in[2];
    const float* Wu     = (const float*)d_in[3];
    const float* Wd     = (const float*)d_in[4];
    float* out = (float*)d_out;

    cudaFuncSetAttribute(k_gemm1, cudaFuncAttributeMaxDynamicSharedMemorySize, SMEM_DYN);
    cudaFuncSetAttribute(k_gemm2, cudaFuncAttributeMaxDynamicSharedMemorySize, SMEM_DYN);

    k_init<<<1, 32>>>();
    k_topk<<<NBLK_TOPK, 256>>>(scores);
    k_aux<<<1, 32>>>(out + (out_size - 1));

    k_split_x<<<N_TOK * HDIM / 4 / 256, 256>>>((const float4*)X);
    k_split_w<<<NEXP * HDIM * HDIM / 4 / 256, 256>>>((const float4*)Wg, 0);
    k_split_w<<<NEXP * HDIM * HDIM / 4 / 256, 256>>>((const float4*)Wu, 1);
    k_split_w<<<NEXP * HDIM * HDIM / 4 / 256, 256>>>((const float4*)Wd, 2);

    dim3 g1(HDIM / 64, NPAIR / 128, NEXP);   // (16, 256, 16)
    k_gemm1<<<g1, 256, SMEM_DYN>>>();

    dim3 g2(HDIM / 128, NPAIR / 128, NEXP);  // (8, 256, 16)
    k_gemm2<<<g2, 256, SMEM_DYN>>>(out);
}

// round 4
// speedup vs baseline: 2.5982x; 1.1074x over previous
#include <cuda_runtime.h>
#include <cuda_bf16.h>
#include <stdint.h>
#include <math.h>

#define N_TOK 8192
#define HDIM  1024
#define NEXP  16
#define TOPK  4
#define NPAIR (N_TOK * TOPK)          // 32768
#define NBLK_TOPK (N_TOK / 256)       // 32
#define CHUNK 64                      // K per pipeline stage
#define NCHUNK (HDIM / CHUNK)         // 16
#define LDS 144                       // smem row stride bytes (conflict-free for ldmatrix)
#define STAGE 73728                   // bytes per stage
#define NSTAGE 3
#define SMEM_DYN (NSTAGE * STAGE)     // 221184
#define MAXTILES 272                  // sum ceil(cnt_e/128) <= 32768/128 + 16

// ---------------- device scratch ----------------
__device__ int   g_counts[NEXP];
__device__ int   g_pairs[NEXP * NPAIR];
__device__ float g_partial[NBLK_TOPK * NEXP];
__device__ int   g_ntiles;
__device__ int2  g_tiles[MAXTILES];
__device__ __nv_bfloat16 g_Xhi[(size_t)N_TOK * HDIM];
__device__ __nv_bfloat16 g_Xlo[(size_t)N_TOK * HDIM];
__device__ __nv_bfloat16 g_Wghi[(size_t)NEXP * HDIM * HDIM];
__device__ __nv_bfloat16 g_Wglo[(size_t)NEXP * HDIM * HDIM];
__device__ __nv_bfloat16 g_Wuhi[(size_t)NEXP * HDIM * HDIM];
__device__ __nv_bfloat16 g_Wulo[(size_t)NEXP * HDIM * HDIM];
__device__ __nv_bfloat16 g_Wdhi[(size_t)NEXP * HDIM * HDIM];
__device__ __nv_bfloat16 g_Wdlo[(size_t)NEXP * HDIM * HDIM];
__device__ __nv_bfloat16 g_thi[(size_t)NPAIR * HDIM];
__device__ __nv_bfloat16 g_tlo[(size_t)NPAIR * HDIM];

// ---------------- helpers ----------------
__device__ __forceinline__ uint32_t smem_u32(const void* p) {
    uint32_t a;
    asm("{ .reg .u64 t; cvta.to.shared.u64 t, %1; cvt.u32.u64 %0, t; }" : "=r"(a) : "l"(p));
    return a;
}
__device__ __forceinline__ void ldm4(uint32_t* r, uint32_t a) {
    asm volatile("ldmatrix.sync.aligned.m8n8.x4.shared.b16 {%0,%1,%2,%3}, [%4];"
                 : "=r"(r[0]), "=r"(r[1]), "=r"(r[2]), "=r"(r[3]) : "r"(a));
}
__device__ __forceinline__ void mma16816(float* d, const uint32_t* a, const uint32_t* b) {
    asm volatile("mma.sync.aligned.m16n8k16.row.col.f32.bf16.bf16.f32 "
                 "{%0,%1,%2,%3},{%4,%5,%6,%7},{%8,%9},{%0,%1,%2,%3};"
                 : "+f"(d[0]), "+f"(d[1]), "+f"(d[2]), "+f"(d[3])
                 : "r"(a[0]), "r"(a[1]), "r"(a[2]), "r"(a[3]), "r"(b[0]), "r"(b[1]));
}
#define CPA(dst, src, sz) asm volatile("cp.async.cg.shared.global [%0],[%1],16,%2;" :: "r"(dst), "l"(src), "r"(sz))
#define CPC()   asm volatile("cp.async.commit_group;")
#define CPW(n)  asm volatile("cp.async.wait_group %0;" :: "n"(n))

__device__ __forceinline__ void split4(float4 v, uint2& h, uint2& l) {
    __nv_bfloat16 hx = __float2bfloat16(v.x), hy = __float2bfloat16(v.y);
    __nv_bfloat16 hz = __float2bfloat16(v.z), hw = __float2bfloat16(v.w);
    __nv_bfloat16 lx = __float2bfloat16(v.x - __bfloat162float(hx));
    __nv_bfloat16 ly = __float2bfloat16(v.y - __bfloat162float(hy));
    __nv_bfloat16 lz = __float2bfloat16(v.z - __bfloat162float(hz));
    __nv_bfloat16 lw = __float2bfloat16(v.w - __bfloat162float(hw));
    h.x = (uint32_t)__bfloat16_as_ushort(hx) | ((uint32_t)__bfloat16_as_ushort(hy) << 16);
    h.y = (uint32_t)__bfloat16_as_ushort(hz) | ((uint32_t)__bfloat16_as_ushort(hw) << 16);
    l.x = (uint32_t)__bfloat16_as_ushort(lx) | ((uint32_t)__bfloat16_as_ushort(ly) << 16);
    l.y = (uint32_t)__bfloat16_as_ushort(lz) | ((uint32_t)__bfloat16_as_ushort(lw) << 16);
}

// ---------------- routing + aux + tile list ----------------
__global__ void k_init() { if (threadIdx.x < NEXP) g_counts[threadIdx.x] = 0; }

__global__ void k_topk(const float* __restrict__ scores) {
    __shared__ float ssum[256][NEXP];
    const int tid = threadIdx.x;
    const int n = blockIdx.x * 256 + tid;
    float v[NEXP];
#pragma unroll
    for (int e = 0; e < NEXP; e++) v[e] = scores[(size_t)n * NEXP + e];
#pragma unroll
    for (int e = 0; e < NEXP; e++) ssum[tid][e] = v[e];
    bool used[NEXP];
#pragma unroll
    for (int e = 0; e < NEXP; e++) used[e] = false;
#pragma unroll
    for (int slot = 0; slot < TOPK; slot++) {
        float best = -1e30f; int bi = 0;
#pragma unroll
        for (int e = 0; e < NEXP; e++)
            if (!used[e] && v[e] > best) { best = v[e]; bi = e; }
        used[bi] = true;
        int pos = atomicAdd(&g_counts[bi], 1);
        g_pairs[bi * NPAIR + pos] = n * TOPK + slot;
    }
    __syncthreads();
    for (int s = 128; s > 0; s >>= 1) {
        if (tid < s)
#pragma unroll
            for (int e = 0; e < NEXP; e++) ssum[tid][e] += ssum[tid + s][e];
        __syncthreads();
    }
    if (tid < NEXP) g_partial[blockIdx.x * NEXP + tid] = ssum[0][tid];
}

__global__ void k_aux(float* __restrict__ dst) {
    __shared__ float se[NEXP];
    const int e = threadIdx.x;
    if (e < NEXP) {
        float s = 0.0f;
        for (int b = 0; b < NBLK_TOPK; b++) s += g_partial[b * NEXP + e];
        se[e] = s * (float)g_counts[e];
    }
    __syncthreads();
    if (e == 0) {
        float t = 0.0f;
#pragma unroll
        for (int i = 0; i < NEXP; i++) t += se[i];
        dst[0] = t * (0.001f * (float)NEXP / ((float)N_TOK * (float)NPAIR));
        // build compact m-tile worklist
        int tcount = 0;
        for (int ex = 0; ex < NEXP; ex++) {
            int c = g_counts[ex];
            for (int mb = 0; mb < c; mb += 128) g_tiles[tcount++] = make_int2(ex, mb);
        }
        g_ntiles = tcount;
    }
}

// ---------------- precompute bf16 hi/lo splits ----------------
__global__ void k_split_x(const float4* __restrict__ src) {
    int i = blockIdx.x * 256 + threadIdx.x;
    float4 v = src[i];
    uint2 h, l; split4(v, h, l);
    ((uint2*)g_Xhi)[i] = h;
    ((uint2*)g_Xlo)[i] = l;
}
__global__ void k_split_w(const float4* __restrict__ Wg, const float4* __restrict__ Wu,
                          const float4* __restrict__ Wd) {
    int i = blockIdx.x * 256 + threadIdx.x;
    int which = blockIdx.y;
    const float4* src = (which == 0) ? Wg : (which == 1) ? Wu : Wd;
    __nv_bfloat16* hi = (which == 0) ? g_Wghi : (which == 1) ? g_Wuhi : g_Wdhi;
    __nv_bfloat16* lo = (which == 0) ? g_Wglo : (which == 1) ? g_Wulo : g_Wdlo;
    float4 v = src[i];
    uint2 h, l; split4(v, h, l);
    ((uint2*)hi)[i] = h;
    ((uint2*)lo)[i] = l;
}

// ---------------- GEMM1: gate+up (bf16x3 HMMA) + silu*mul ----------------
// 3-stage cp.async pipeline, 1 sync/chunk. Stage: AH 0, AL 18432,
// BGH 36864, BGL 46080, BUH 55296, BUL 64512.
__global__ __launch_bounds__(256, 1) void k_gemm1() {
    if ((int)blockIdx.y >= g_ntiles) return;
    const int2 te = g_tiles[blockIdx.y];
    const int e = te.x, mbase = te.y;
    const int cnt = g_counts[e];

    extern __shared__ char dyn[];
    __shared__ int spid[128];
    const int tid = threadIdx.x;
    if (tid < 128) {
        int r = mbase + tid;
        spid[tid] = (r < cnt) ? g_pairs[e * NPAIR + r] : -1;
    }
    __syncthreads();

    const uint32_t sbase = smem_u32(dyn);
    const int n0 = blockIdx.x * 64;
    const __nv_bfloat16* GH = g_Wghi + (size_t)e * HDIM * HDIM;
    const __nv_bfloat16* GL = g_Wglo + (size_t)e * HDIM * HDIM;
    const __nv_bfloat16* UH = g_Wuhi + (size_t)e * HDIM * HDIM;
    const __nv_bfloat16* UL = g_Wulo + (size_t)e * HDIM * HDIM;

    const int lr = tid >> 3;
    const int lc = tid & 7;

    auto load_stage = [&](int s, int k0) {
        uint32_t st = sbase + s * STAGE;
#pragma unroll
        for (int i = 0; i < 4; i++) {
            int r = lr + i * 32;
            int p = spid[r];
            int tok = (p >= 0) ? (p >> 2) : 0;
            size_t so = (size_t)tok * HDIM + k0 + lc * 8;
            uint32_t d = st + r * LDS + lc * 16;
            int sz = (p >= 0) ? 16 : 0;
            CPA(d,         g_Xhi + so, sz);
            CPA(d + 18432, g_Xlo + so, sz);
        }
#pragma unroll
        for (int i = 0; i < 2; i++) {
            int r = lr + i * 32;
            size_t so = (size_t)(n0 + r) * HDIM + k0 + lc * 8;
            uint32_t d = st + 36864 + r * LDS + lc * 16;
            CPA(d,         GH + so, 16);
            CPA(d + 9216,  GL + so, 16);
            CPA(d + 18432, UH + so, 16);
            CPA(d + 27648, UL + so, 16);
        }
        CPC();
    };

    const int wid = tid >> 5, lane = tid & 31;
    const int wm = (wid & 3) * 32;
    const int wn = (wid >> 2) * 32;
    const uint32_t rowA = (uint32_t)(wm + (lane & 15)) * LDS + ((lane >> 4) & 1) * 16;
    const uint32_t rowB = (uint32_t)(wn + ((lane >> 4) & 1) * 8 + (lane & 7)) * LDS + ((lane >> 3) & 1) * 16;

    float accg[32], accu[32];
#pragma unroll
    for (int i = 0; i < 32; i++) { accg[i] = 0.f; accu[i] = 0.f; }

    load_stage(0, 0);
    load_stage(1, CHUNK);

    int s_cur = 0;
    for (int c = 0; c < NCHUNK; c++) {
        CPW(1);
        __syncthreads();
        if (c + 2 < NCHUNK) {
            int s2 = s_cur + 2; if (s2 >= NSTAGE) s2 -= NSTAGE;
            load_stage(s2, (c + 2) * CHUNK);
        } else CPC();

        uint32_t st = sbase + s_cur * STAGE;
#pragma unroll
        for (int kk = 0; kk < 4; kk++) {
            uint32_t Ah[8], Al[8], BGh[8], BGl[8], BUh[8], BUl[8];
#pragma unroll
            for (int mi = 0; mi < 2; mi++) {
                ldm4(&Ah[mi * 4], st + rowA + mi * 16 * LDS + kk * 32);
                ldm4(&Al[mi * 4], st + 18432 + rowA + mi * 16 * LDS + kk * 32);
            }
#pragma unroll
            for (int nj = 0; nj < 2; nj++) {
                ldm4(&BGh[nj * 4], st + 36864 + rowB + nj * 16 * LDS + kk * 32);
                ldm4(&BGl[nj * 4], st + 46080 + rowB + nj * 16 * LDS + kk * 32);
                ldm4(&BUh[nj * 4], st + 55296 + rowB + nj * 16 * LDS + kk * 32);
                ldm4(&BUl[nj * 4], st + 64512 + rowB + nj * 16 * LDS + kk * 32);
            }
#pragma unroll
            for (int mi = 0; mi < 2; mi++)
#pragma unroll
                for (int ni = 0; ni < 4; ni++) {
                    float* dg = &accg[(mi * 4 + ni) * 4];
                    float* du = &accu[(mi * 4 + ni) * 4];
                    mma16816(dg, &Ah[mi * 4], &BGh[ni * 2]);
                    mma16816(dg, &Al[mi * 4], &BGh[ni * 2]);
                    mma16816(dg, &Ah[mi * 4], &BGl[ni * 2]);
                    mma16816(du, &Ah[mi * 4], &BUh[ni * 2]);
                    mma16816(du, &Al[mi * 4], &BUh[ni * 2]);
                    mma16816(du, &Ah[mi * 4], &BUl[ni * 2]);
                }
        }
        s_cur = s_cur + 1; if (s_cur >= NSTAGE) s_cur = 0;
    }

    const int r0 = wm + (lane >> 2);
    const int coff = (lane & 3) * 2;
#pragma unroll
    for (int mi = 0; mi < 2; mi++) {
#pragma unroll
        for (int half = 0; half < 2; half++) {
            int row = r0 + mi * 16 + half * 8;
            int p = spid[row];
            if (p < 0) continue;
#pragma unroll
            for (int ni = 0; ni < 4; ni++) {
                const float* dg = &accg[(mi * 4 + ni) * 4 + half * 2];
                const float* du = &accu[(mi * 4 + ni) * 4 + half * 2];
                float v0 = du[0] * dg[0] / (1.0f + __expf(-dg[0]));
                float v1 = du[1] * dg[1] / (1.0f + __expf(-dg[1]));
                __nv_bfloat16 h0 = __float2bfloat16(v0), h1 = __float2bfloat16(v1);
                __nv_bfloat16 l0 = __float2bfloat16(v0 - __bfloat162float(h0));
                __nv_bfloat16 l1 = __float2bfloat16(v1 - __bfloat162float(h1));
                uint32_t hp = (uint32_t)__bfloat16_as_ushort(h0) | ((uint32_t)__bfloat16_as_ushort(h1) << 16);
                uint32_t lp = (uint32_t)__bfloat16_as_ushort(l0) | ((uint32_t)__bfloat16_as_ushort(l1) << 16);
                size_t off = (size_t)p * HDIM + n0 + wn + ni * 8 + coff;
                *(uint32_t*)(g_thi + off) = hp;
                *(uint32_t*)(g_tlo + off) = lp;
            }
        }
    }
}

// ---------------- GEMM2: down proj (bf16x3 HMMA) + relu ----------------
// Stage: AH 0, AL 18432, BH 36864, BL 55296.
__global__ __launch_bounds__(256, 1) void k_gemm2(float* __restrict__ out) {
    if ((int)blockIdx.y >= g_ntiles) return;
    const int2 te = g_tiles[blockIdx.y];
    const int e = te.x, mbase = te.y;
    const int cnt = g_counts[e];

    extern __shared__ char dyn[];
    __shared__ int spid[128];
    const int tid = threadIdx.x;
    if (tid < 128) {
        int r = mbase + tid;
        spid[tid] = (r < cnt) ? g_pairs[e * NPAIR + r] : -1;
    }
    __syncthreads();

    const uint32_t sbase = smem_u32(dyn);
    const int n0 = blockIdx.x * 128;
    const __nv_bfloat16* WH = g_Wdhi + (size_t)e * HDIM * HDIM;
    const __nv_bfloat16* WL = g_Wdlo + (size_t)e * HDIM * HDIM;

    const int lr = tid >> 3;
    const int lc = tid & 7;

    auto load_stage = [&](int s, int k0) {
        uint32_t st = sbase + s * STAGE;
#pragma unroll
        for (int i = 0; i < 4; i++) {
            int r = lr + i * 32;
            int p = spid[r];
            int pp = (p >= 0) ? p : 0;
            size_t so = (size_t)pp * HDIM + k0 + lc * 8;
            uint32_t d = st + r * LDS + lc * 16;
            int sz = (p >= 0) ? 16 : 0;
            CPA(d,         g_thi + so, sz);
            CPA(d + 18432, g_tlo + so, sz);
        }
#pragma unroll
        for (int i = 0; i < 4; i++) {
            int r = lr + i * 32;
            size_t so = (size_t)(n0 + r) * HDIM + k0 + lc * 8;
            uint32_t d = st + 36864 + r * LDS + lc * 16;
            CPA(d,         WH + so, 16);
            CPA(d + 18432, WL + so, 16);
        }
        CPC();
    };

    const int wid = tid >> 5, lane = tid & 31;
    const int wm = (wid & 3) * 32;
    const int wn = (wid >> 2) * 64;
    const uint32_t rowA = (uint32_t)(wm + (lane & 15)) * LDS + ((lane >> 4) & 1) * 16;
    const uint32_t rowB = (uint32_t)(wn + ((lane >> 4) & 1) * 8 + (lane & 7)) * LDS + ((lane >> 3) & 1) * 16;

    float acc[64];
#pragma unroll
    for (int i = 0; i < 64; i++) acc[i] = 0.f;

    load_stage(0, 0);
    load_stage(1, CHUNK);

    int s_cur = 0;
    for (int c = 0; c < NCHUNK; c++) {
        CPW(1);
        __syncthreads();
        if (c + 2 < NCHUNK) {
            int s2 = s_cur + 2; if (s2 >= NSTAGE) s2 -= NSTAGE;
            load_stage(s2, (c + 2) * CHUNK);
        } else CPC();

        uint32_t st = sbase + s_cur * STAGE;
#pragma unroll
        for (int kk = 0; kk < 4; kk++) {
            uint32_t Ah[8], Al[8], Bh[16], Bl[16];
#pragma unroll
            for (int mi = 0; mi < 2; mi++) {
                ldm4(&Ah[mi * 4], st + rowA + mi * 16 * LDS + kk * 32);
                ldm4(&Al[mi * 4], st + 18432 + rowA + mi * 16 * LDS + kk * 32);
            }
#pragma unroll
            for (int nj = 0; nj < 4; nj++) {
                ldm4(&Bh[nj * 4], st + 36864 + rowB + nj * 16 * LDS + kk * 32);
                ldm4(&Bl[nj * 4], st + 55296 + rowB + nj * 16 * LDS + kk * 32);
            }
#pragma unroll
            for (int mi = 0; mi < 2; mi++)
#pragma unroll
                for (int ni = 0; ni < 8; ni++) {
                    float* d = &acc[(mi * 8 + ni) * 4];
                    mma16816(d, &Ah[mi * 4], &Bh[ni * 2]);
                    mma16816(d, &Al[mi * 4], &Bh[ni * 2]);
                    mma16816(d, &Ah[mi * 4], &Bl[ni * 2]);
                }
        }
        s_cur = s_cur + 1; if (s_cur >= NSTAGE) s_cur = 0;
    }

    const int r0 = wm + (lane >> 2);
    const int coff = (lane & 3) * 2;
#pragma unroll
    for (int mi = 0; mi < 2; mi++) {
#pragma unroll
        for (int half = 0; half < 2; half++) {
            int row = r0 + mi * 16 + half * 8;
            int p = spid[row];
            if (p < 0) continue;
#pragma unroll
            for (int ni = 0; ni < 8; ni++) {
                const float* d = &acc[(mi * 8 + ni) * 4 + half * 2];
                float2 v;
                v.x = fmaxf(d[0], 0.f);
                v.y = fmaxf(d[1], 0.f);
                *(float2*)(out + (size_t)p * HDIM + n0 + wn + ni * 8 + coff) = v;
            }
        }
    }
}

// ---------------- launch ----------------
extern "C" void kernel_launch(void* const* d_in, const int* in_sizes, int n_in,
                              void* d_out, int out_size) {
    const float* X      = (const float*)d_in[0];
    const float* scores = (const float*)d_in[1];
    const float* Wg     = (const float*)d_in[2];
    const float* Wu     = (const float*)d_in[3];
    const float* Wd     = (const float*)d_in[4];
    float* out = (float*)d_out;

    cudaFuncSetAttribute(k_gemm1, cudaFuncAttributeMaxDynamicSharedMemorySize, SMEM_DYN);
    cudaFuncSetAttribute(k_gemm2, cudaFuncAttributeMaxDynamicSharedMemorySize, SMEM_DYN);

    k_init<<<1, 32>>>();
    k_topk<<<NBLK_TOPK, 256>>>(scores);
    k_aux<<<1, 32>>>(out + (out_size - 1));

    k_split_x<<<N_TOK * HDIM / 4 / 256, 256>>>((const float4*)X);
    dim3 gw(NEXP * HDIM * HDIM / 4 / 256, 3);
    k_split_w<<<gw, 256>>>((const float4*)Wg, (const float4*)Wu, (const float4*)Wd);

    dim3 g1(HDIM / 64, MAXTILES);    // (16, 272) — live tiles only do work
    k_gemm1<<<g1, 256, SMEM_DYN>>>();

    dim3 g2(HDIM / 128, MAXTILES);   // (8, 272)
    k_gemm2<<<g2, 256, SMEM_DYN>>>(out);
}